// round 13
// baseline (speedup 1.0000x reference)
#include <cuda_runtime.h>

// Problem constants
#define Bn     16
#define Rn     128
#define Tn     128
#define Hn     32
#define En     64
#define VOCABn 258
#define NTOK   (Bn*Rn*Tn)   // 262144

// Scratch
__device__ float g_out_h[(size_t)NTOK * Hn];
__device__ int   g_progress[Rn * 8];     // use [r*4+g]; reset by proj_kernel
__device__ float g_G[VOCABn * 96];       // W_ih0[:, :64] @ embed_table[v]^T

// ---------------------------------------------------------------------------

__device__ __forceinline__ int ld_poll(const int* p) {
    int v;
    asm volatile("ld.global.cg.b32 %0, [%1];" : "=r"(v) : "l"(p));
    return v;
}
__device__ __forceinline__ void st_rel(int* p, int v) {
    asm volatile("st.global.release.gpu.b32 [%0], %1;" :: "l"(p), "r"(v) : "memory");
}
__device__ __forceinline__ int ld_acq_sh(const int* p) {
    int v; unsigned s = (unsigned)__cvta_generic_to_shared(p);
    asm volatile("ld.acquire.cta.shared.b32 %0, [%1];" : "=r"(v) : "r"(s) : "memory");
    return v;
}
__device__ __forceinline__ void st_rel_sh(int* p, int v) {
    unsigned s = (unsigned)__cvta_generic_to_shared(p);
    asm volatile("st.release.cta.shared.b32 [%0], %1;" :: "r"(s), "r"(v) : "memory");
}
__device__ __forceinline__ float sigm(float x) {
    return __fdividef(1.0f, 1.0f + __expf(-x));
}
__device__ __forceinline__ float tanh_f(float x) {
    float e = __expf(2.0f * x);
    return 1.0f - __fdividef(2.0f, e + 1.0f);
}
__device__ __forceinline__ unsigned long long fma2(unsigned long long a, unsigned long long b,
                                                   unsigned long long c) {
    unsigned long long d;
    asm("fma.rn.f32x2 %0, %1, %2, %3;" : "=l"(d) : "l"(a), "l"(b), "l"(c));
    return d;
}
__device__ __forceinline__ float hsum(unsigned long long a) {
    float lo, hi;
    asm("mov.b64 {%0, %1}, %2;" : "=f"(lo), "=f"(hi) : "l"(a));
    return lo + hi;
}

// ---------------------------------------------------------------------------
// 4-batch i-paired triple-plane dot: acc{R,Z,N}[b] += sum_i w{p}[j][i]*in[b][i]
// Weights: plane[j*36 + i] (conflict-free LDS.128); inputs in[b*32+i] broadcast.
__device__ __forceinline__ void dotacc4(
    const float* __restrict__ pR, const float* __restrict__ pZ, const float* __restrict__ pN,
    const float* __restrict__ in, int j,
    unsigned long long aR[4], unsigned long long aZ[4], unsigned long long aN[4])
{
    const float* wR = pR + j * 36;
    const float* wZ = pZ + j * 36;
    const float* wN = pN + j * 36;
#pragma unroll
    for (int g = 0; g < 8; ++g) {
        const int i0 = g * 4;
        ulonglong2 w0 = *(const ulonglong2*)(wR + i0);
        ulonglong2 w1 = *(const ulonglong2*)(wZ + i0);
        ulonglong2 w2 = *(const ulonglong2*)(wN + i0);
        ulonglong2 v0 = *(const ulonglong2*)(in + 0 * 32 + i0);
        ulonglong2 v1 = *(const ulonglong2*)(in + 1 * 32 + i0);
        ulonglong2 v2 = *(const ulonglong2*)(in + 2 * 32 + i0);
        ulonglong2 v3 = *(const ulonglong2*)(in + 3 * 32 + i0);
        aR[0] = fma2(w0.x, v0.x, aR[0]); aZ[0] = fma2(w1.x, v0.x, aZ[0]); aN[0] = fma2(w2.x, v0.x, aN[0]);
        aR[1] = fma2(w0.x, v1.x, aR[1]); aZ[1] = fma2(w1.x, v1.x, aZ[1]); aN[1] = fma2(w2.x, v1.x, aN[1]);
        aR[2] = fma2(w0.x, v2.x, aR[2]); aZ[2] = fma2(w1.x, v2.x, aZ[2]); aN[2] = fma2(w2.x, v2.x, aN[2]);
        aR[3] = fma2(w0.x, v3.x, aR[3]); aZ[3] = fma2(w1.x, v3.x, aZ[3]); aN[3] = fma2(w2.x, v3.x, aN[3]);
        aR[0] = fma2(w0.y, v0.y, aR[0]); aZ[0] = fma2(w1.y, v0.y, aZ[0]); aN[0] = fma2(w2.y, v0.y, aN[0]);
        aR[1] = fma2(w0.y, v1.y, aR[1]); aZ[1] = fma2(w1.y, v1.y, aZ[1]); aN[1] = fma2(w2.y, v1.y, aN[1]);
        aR[2] = fma2(w0.y, v2.y, aR[2]); aZ[2] = fma2(w1.y, v2.y, aZ[2]); aN[2] = fma2(w2.y, v2.y, aN[2]);
        aR[3] = fma2(w0.y, v3.y, aR[3]); aZ[3] = fma2(w1.y, v3.y, aZ[3]); aN[3] = fma2(w2.y, v3.y, aN[3]);
    }
}

// ---------------------------------------------------------------------------
// prep: G[v][g] = sum_e wih0[g][e] * embed_table[v][e]
__global__ void prep_kernel(const float* __restrict__ wih0,
                            const float* __restrict__ emb)
{
    const int v = blockIdx.x;
    const int g = threadIdx.x;    // 96 threads
    const float* wr = wih0 + g * 65;
    const float* er = emb + v * En;
    float acc = 0.0f;
#pragma unroll 8
    for (int e = 0; e < En; ++e) acc += wr[e] * er[e];
    g_G[v * 96 + g] = acc;
}

// ---------------------------------------------------------------------------
// Smem layout (floats). Planes: R, Z, N per matrix, row stride 36.
#define PL_SM    1152                  // 32*36
#define P_HH0    0
#define P_IH1    (1*3456)
#define P_HH1    (2*3456)
#define P_IH2    (3*3456)
#define P_HH2    (4*3456)
#define P_M      (5*3456)              // folded W_ih0 @ W_h2e^T
#define P_STG    (6*3456)              // 20736
// per-group staging (stride 704 floats):
//   ring0 +0, ring1 +128, st_h1 +256, st_h2 +384, st_pv +512,
//   a_done flag @ +640 (int), b_done flag @ +656 (int)
#define STG_GRP  704
#define P_BF     (P_STG + 4*STG_GRP)   // folded layer-0 gate bias [96]
#define SM_FLOATS (P_BF + 128)
#define SMEM_BYTES (SM_FLOATS * 4)

extern __shared__ float s_rnn[];

__global__ __launch_bounds__(256, 1) void rnn_kernel(
    const int*   __restrict__ x,
    const float* __restrict__ wih0, const float* __restrict__ whh0,
    const float* __restrict__ bih0, const float* __restrict__ bhh0,
    const float* __restrict__ wih1, const float* __restrict__ whh1,
    const float* __restrict__ bih1, const float* __restrict__ bhh1,
    const float* __restrict__ wih2, const float* __restrict__ whh2,
    const float* __restrict__ bih2, const float* __restrict__ bhh2,
    const float* __restrict__ wh2e, const float* __restrict__ bh2e)
{
    const int r   = blockIdx.x;
    const int tid = threadIdx.x;
    const float rf = (float)r * (2.0f / 128.0f) - 1.0f;

    for (int n = tid; n < SM_FLOATS; n += 256) s_rnn[n] = 0.0f;
    __syncthreads();

    // stage recurrent weights into gate planes
    {
        const float* srcs[5] = { whh0, wih1, whh1, wih2, whh2 };
        const int    offs[5] = { P_HH0, P_IH1, P_HH1, P_IH2, P_HH2 };
#pragma unroll
        for (int m = 0; m < 5; ++m) {
            const float* src = srcs[m];
            float* dst = s_rnn + offs[m];
            for (int n = tid; n < 96 * 32; n += 256) {
                int gI = n >> 5, i = n & 31;
                dst[(gI >> 5) * PL_SM + (gI & 31) * 36 + i] = src[n];
            }
        }
    }
    // fold M[g][h] = sum_e wih0[g][e] * wh2e[e][h]
    for (int n = tid; n < 96 * 32; n += 256) {
        int gI = n >> 5, h = n & 31;
        const float* wr = wih0 + gI * 65;
        float acc = wr[64] * __ldg(&wh2e[64 * 32 + h]);
#pragma unroll 4
        for (int e = 0; e < 64; ++e) acc += wr[e] * __ldg(&wh2e[e * 32 + h]);
        s_rnn[P_M + (gI >> 5) * PL_SM + (gI & 31) * 36 + h] = acc;
    }
    // fold bf[g] = bih0[g] + sum_e wih0[g][e]*bh2e[e] + wih0[g][64]*rf
    if (tid < 96) {
        const float* wr = wih0 + tid * 65;
        float acc = bih0[tid] + wr[64] * rf;
#pragma unroll 5
        for (int e = 0; e < 65; ++e) acc += wr[e] * __ldg(&bh2e[e]);
        s_rnn[P_BF + tid] = acc;
    }
    __syncthreads();

    const int wid  = tid >> 5;
    const int j    = tid & 31;
    const bool isA = (wid < 4);
    const int g    = wid & 3;        // group; A=warp g, B=warp g+4 (same SMSP)
    const int b0   = 4 * g;

    const float* hh0R = s_rnn + P_HH0, *hh0Z = hh0R + PL_SM, *hh0N = hh0Z + PL_SM;
    const float* ih1R = s_rnn + P_IH1, *ih1Z = ih1R + PL_SM, *ih1N = ih1Z + PL_SM;
    const float* hh1R = s_rnn + P_HH1, *hh1Z = hh1R + PL_SM, *hh1N = hh1Z + PL_SM;
    const float* ih2R = s_rnn + P_IH2, *ih2Z = ih2R + PL_SM, *ih2N = ih2Z + PL_SM;
    const float* hh2R = s_rnn + P_HH2, *hh2Z = hh2R + PL_SM, *hh2N = hh2Z + PL_SM;
    const float* MR   = s_rnn + P_M,   *MZ   = MR + PL_SM,   *MN   = MZ + PL_SM;

    float* stg    = s_rnn + P_STG + g * STG_GRP;
    float* ring0  = stg;
    float* ring1  = stg + 128;
    float* st_h1  = stg + 256;
    float* st_h2  = stg + 384;
    float* st_pv  = stg + 512;
    int*   a_done = (int*)(stg + 640);
    int*   b_done = (int*)(stg + 656);

    if (isA) {
        // ================= Warp A: layer 0 =================
        const float brc0 = s_rnn[P_BF + j]      + bhh0[j];
        const float bzc0 = s_rnn[P_BF + 32 + j] + bhh0[32 + j];
        const float bin0 = s_rnn[P_BF + 64 + j];
        const float bhn0 = bhh0[64 + j];

        const int* waitflag = (r > 0) ? &g_progress[(r - 1) * 4 + g] : (const int*)0;
        int seen = 0;

        float h0r[4] = {0,0,0,0};

        // prologue: G for t=0, x for t=1
        float gc[12];
        int xvn[4];
        {
            int xv[4];
#pragma unroll
            for (int b = 0; b < 4; ++b) xv[b] = __ldg(&x[((b0 + b) * Rn + r) * Tn]);
#pragma unroll
            for (int b = 0; b < 4; ++b) {
                gc[b*3+0] = __ldg(&g_G[xv[b] * 96 + j]);
                gc[b*3+1] = __ldg(&g_G[xv[b] * 96 + 32 + j]);
                gc[b*3+2] = __ldg(&g_G[xv[b] * 96 + 64 + j]);
            }
#pragma unroll
            for (int b = 0; b < 4; ++b) xvn[b] = __ldg(&x[((b0 + b) * Rn + r) * Tn + 1]);
        }

        for (int t = 0; t < Tn; ++t) {
            // prefetch x[t+2], G[x[t+1]]
            const int tnx = (t + 2 < Tn) ? t + 2 : Tn - 1;
            int xv2[4];
#pragma unroll
            for (int b = 0; b < 4; ++b) xv2[b] = __ldg(&x[((b0 + b) * Rn + r) * Tn + tnx]);
            float gnx[12];
#pragma unroll
            for (int b = 0; b < 4; ++b) {
                gnx[b*3+0] = __ldg(&g_G[xvn[b] * 96 + j]);
                gnx[b*3+1] = __ldg(&g_G[xvn[b] * 96 + 32 + j]);
                gnx[b*3+2] = __ldg(&g_G[xvn[b] * 96 + 64 + j]);
            }

            // hh0 dot over h0(t-1) (ring slot (t+1)&1 == (t-1)&1)
            float* ringPrev = ((t & 1) == 0) ? ring1 : ring0;
            float* ringCur  = ((t & 1) == 0) ? ring0 : ring1;
            unsigned long long ar0[4] = {0,0,0,0}, az0[4] = {0,0,0,0}, anh0[4] = {0,0,0,0};
            dotacc4(hh0R, hh0Z, hh0N, ringPrev, j, ar0, az0, anh0);

            // row poll + pv + M dot
            unsigned long long ani0[4] = {0,0,0,0};
            if (r > 0) {
                if (seen <= t) {
                    seen = ld_poll(waitflag);
                    while (seen <= t) { __nanosleep(20); seen = ld_poll(waitflag); }
                    asm volatile("" ::: "memory");
                }
                __syncwarp(0x0000000F << (g * 0) ? 0xFFFFFFFF : 0xFFFFFFFF);
#pragma unroll
                for (int b = 0; b < 4; ++b)
                    st_pv[b * 32 + j] = __ldcg(&g_out_h[(size_t)(((b0 + b) * Rn + (r - 1)) * Tn + t) * Hn + j]);
                __syncwarp();
                dotacc4(MR, MZ, MN, st_pv, j, ar0, az0, ani0);
            }

            // layer-0 activations
#pragma unroll
            for (int b = 0; b < 4; ++b) {
                float gr = sigm(hsum(ar0[b]) + gc[b*3+0] + brc0);
                float gz = sigm(hsum(az0[b]) + gc[b*3+1] + bzc0);
                float gnv = tanh_f(hsum(ani0[b]) + gc[b*3+2] + bin0 + gr * (hsum(anh0[b]) + bhn0));
                h0r[b] = gnv + gz * (h0r[b] - gnv);
            }

            // backpressure: B must have consumed slot t-2 (b_done >= t-1)
            if (t >= 2) { while (ld_acq_sh(b_done) < t - 1) { } }

            // publish h0(t) to ring + release
#pragma unroll
            for (int b = 0; b < 4; ++b) ringCur[b * 32 + j] = h0r[b];
            st_rel_sh(a_done, t + 1);    // all lanes: each lane's release covers its own STS

            // rotate prefetch
#pragma unroll
            for (int k = 0; k < 12; ++k) gc[k] = gnx[k];
#pragma unroll
            for (int b = 0; b < 4; ++b) xvn[b] = xv2[b];
        }
    } else {
        // ================= Warp B: layers 1 + 2 =================
        const float brc1 = bih1[j] + bhh1[j], bzc1 = bih1[32+j] + bhh1[32+j];
        const float bin1 = bih1[64+j],        bhn1 = bhh1[64+j];
        const float brc2 = bih2[j] + bhh2[j], bzc2 = bih2[32+j] + bhh2[32+j];
        const float bin2 = bih2[64+j],        bhn2 = bhh2[64+j];

        int* myflag = &g_progress[r * 4 + g];

        float h1r[4] = {0,0,0,0}, h2r[4] = {0,0,0,0};

        for (int t = 0; t < Tn; ++t) {
            // pre-wait: recurrent dots over own h1(t-1), h2(t-1)
            unsigned long long ar1[4] = {0,0,0,0}, az1[4] = {0,0,0,0}, anh1[4] = {0,0,0,0};
            unsigned long long ar2[4] = {0,0,0,0}, az2[4] = {0,0,0,0}, anh2[4] = {0,0,0,0};
            dotacc4(hh1R, hh1Z, hh1N, st_h1, j, ar1, az1, anh1);
            dotacc4(hh2R, hh2Z, hh2N, st_h2, j, ar2, az2, anh2);

            // wait for h0(t) from A
            while (ld_acq_sh(a_done) < t + 1) { }
            const float* ringCur = ((t & 1) == 0) ? ring0 : ring1;

            // layer 1
            {
                unsigned long long ani[4] = {0,0,0,0};
                dotacc4(ih1R, ih1Z, ih1N, ringCur, j, ar1, az1, ani);
#pragma unroll
                for (int b = 0; b < 4; ++b) {
                    float gr = sigm(hsum(ar1[b]) + brc1);
                    float gz = sigm(hsum(az1[b]) + bzc1);
                    float gnv = tanh_f(hsum(ani[b]) + bin1 + gr * (hsum(anh1[b]) + bhn1));
                    h1r[b] = gnv + gz * (h1r[b] - gnv);
                }
                __syncwarp();
#pragma unroll
                for (int b = 0; b < 4; ++b) st_h1[b * 32 + j] = h1r[b];
                __syncwarp();
            }

            // layer 2
            {
                unsigned long long ani[4] = {0,0,0,0};
                dotacc4(ih2R, ih2Z, ih2N, st_h1, j, ar2, az2, ani);
#pragma unroll
                for (int b = 0; b < 4; ++b) {
                    float gr = sigm(hsum(ar2[b]) + brc2);
                    float gz = sigm(hsum(az2[b]) + bzc2);
                    float gnv = tanh_f(hsum(ani[b]) + bin2 + gr * (hsum(anh2[b]) + bhn2));
                    h2r[b] = gnv + gz * (h2r[b] - gnv);
                }
                __syncwarp();
#pragma unroll
                for (int b = 0; b < 4; ++b) st_h2[b * 32 + j] = h2r[b];
                __syncwarp();
            }

            // publish to next row + intra-pair consume-release
#pragma unroll
            for (int b = 0; b < 4; ++b)
                __stcg(&g_out_h[(size_t)(((b0 + b) * Rn + r) * Tn + t) * Hn + j], h2r[b]);
            st_rel(myflag, t + 1);
            st_rel_sh(b_done, t + 1);   // release orders prior ring reads too
        }
    }
}

// ---------------------------------------------------------------------------
// Output projection: weights in registers, pre-duplicated h pairs in dynamic smem.
#define PT 128
#define PROJ_DYN_BYTES (PT * 72 * 4)

extern __shared__ float h_s[];   // [PT][72]: h duplicated {h,h}, stride 72 floats

__global__ __launch_bounds__(256) void proj_kernel(
    const float* __restrict__ w_out,
    const float* __restrict__ b_out,
    float* __restrict__ pred)
{
    __shared__ float w_s[32 * 260];     // [h][v] padded
    __shared__ float b_s[260];

    const int tid = threadIdx.x;

    if (blockIdx.x == 0) {
        for (int n = tid; n < Rn * 4; n += 256) g_progress[n] = 0;   // reset for next replay
    }

    for (int n = tid; n < VOCABn * 32; n += 256) {
        int v = n >> 5, h = n & 31;
        w_s[h * 260 + v] = w_out[n];
    }
    for (int n = tid; n < VOCABn; n += 256) b_s[n] = b_out[n];

    const size_t tok0 = (size_t)blockIdx.x * PT;
    const float* src = g_out_h + tok0 * 32;
    for (int n = tid; n < PT * 32; n += 256) {
        int i = n >> 5, h = n & 31;
        float v = src[n];
        h_s[i * 72 + 2 * h]     = v;
        h_s[i * 72 + 2 * h + 1] = v;
    }
    __syncthreads();

    const int warp = tid >> 5, lane = tid & 31;
    const int p = ((warp & 3) << 5) + lane;        // 0..127
    const int tokbase = (warp >> 2) * 64;

    unsigned long long wreg[32];
#pragma unroll
    for (int h = 0; h < 32; ++h)
        wreg[h] = *(const unsigned long long*)&w_s[h * 260 + 2 * p];
    const unsigned long long b2 = *(const unsigned long long*)&b_s[2 * p];

#pragma unroll 1
    for (int tg = 0; tg < 16; ++tg) {
        const int tk = tokbase + tg * 4;
        unsigned long long a0 = b2, a1 = b2, a2 = b2, a3 = b2;
        const float* h0p = &h_s[(tk + 0) * 72];
        const float* h1p = &h_s[(tk + 1) * 72];
        const float* h2p = &h_s[(tk + 2) * 72];
        const float* h3p = &h_s[(tk + 3) * 72];
#pragma unroll
        for (int hq = 0; hq < 8; ++hq) {
            ulonglong2 qa0 = *(const ulonglong2*)(h0p + hq * 8);
            ulonglong2 qb0 = *(const ulonglong2*)(h0p + hq * 8 + 4);
            ulonglong2 qa1 = *(const ulonglong2*)(h1p + hq * 8);
            ulonglong2 qb1 = *(const ulonglong2*)(h1p + hq * 8 + 4);
            ulonglong2 qa2 = *(const ulonglong2*)(h2p + hq * 8);
            ulonglong2 qb2 = *(const ulonglong2*)(h2p + hq * 8 + 4);
            ulonglong2 qa3 = *(const ulonglong2*)(h3p + hq * 8);
            ulonglong2 qb3 = *(const ulonglong2*)(h3p + hq * 8 + 4);
            a0 = fma2(wreg[hq*4+0], qa0.x, a0);
            a1 = fma2(wreg[hq*4+0], qa1.x, a1);
            a2 = fma2(wreg[hq*4+0], qa2.x, a2);
            a3 = fma2(wreg[hq*4+0], qa3.x, a3);
            a0 = fma2(wreg[hq*4+1], qa0.y, a0);
            a1 = fma2(wreg[hq*4+1], qa1.y, a1);
            a2 = fma2(wreg[hq*4+1], qa2.y, a2);
            a3 = fma2(wreg[hq*4+1], qa3.y, a3);
            a0 = fma2(wreg[hq*4+2], qb0.x, a0);
            a1 = fma2(wreg[hq*4+2], qb1.x, a1);
            a2 = fma2(wreg[hq*4+2], qb2.x, a2);
            a3 = fma2(wreg[hq*4+2], qb3.x, a3);
            a0 = fma2(wreg[hq*4+3], qb0.y, a0);
            a1 = fma2(wreg[hq*4+3], qb1.y, a1);
            a2 = fma2(wreg[hq*4+3], qb2.y, a2);
            a3 = fma2(wreg[hq*4+3], qb3.y, a3);
        }
        float* outp = &pred[(tok0 + tk) * VOCABn + 2 * p];
        *(unsigned long long*)(outp + 0 * VOCABn) = a0;
        *(unsigned long long*)(outp + 1 * VOCABn) = a1;
        *(unsigned long long*)(outp + 2 * VOCABn) = a2;
        *(unsigned long long*)(outp + 3 * VOCABn) = a3;
    }

    // tail pair 128 (v = 256, 257)
    if (tid < PT) {
        unsigned long long acc = *(const unsigned long long*)&b_s[256];
        const float* hp = &h_s[tid * 72];
#pragma unroll
        for (int h = 0; h < 32; ++h)
            acc = fma2(*(const unsigned long long*)&w_s[h * 260 + 256],
                       *(const unsigned long long*)(hp + 2 * h), acc);
        *(unsigned long long*)&pred[(tok0 + tid) * VOCABn + 256] = acc;
    }
}

// ---------------------------------------------------------------------------

extern "C" void kernel_launch(void* const* d_in, const int* in_sizes, int n_in,
                              void* d_out, int out_size)
{
    const int*   x     = (const int*)  d_in[0];
    const float* emb   = (const float*)d_in[1];
    const float* wih0  = (const float*)d_in[2];
    const float* whh0  = (const float*)d_in[3];
    const float* bih0  = (const float*)d_in[4];
    const float* bhh0  = (const float*)d_in[5];
    const float* wih1  = (const float*)d_in[6];
    const float* whh1  = (const float*)d_in[7];
    const float* bih1  = (const float*)d_in[8];
    const float* bhh1  = (const float*)d_in[9];
    const float* wih2  = (const float*)d_in[10];
    const float* whh2  = (const float*)d_in[11];
    const float* bih2  = (const float*)d_in[12];
    const float* bhh2  = (const float*)d_in[13];
    const float* wh2e  = (const float*)d_in[14];
    const float* bh2e  = (const float*)d_in[15];
    const float* w_out = (const float*)d_in[16];
    const float* b_out = (const float*)d_in[17];
    float* pred = (float*)d_out;

    cudaFuncSetAttribute(rnn_kernel, cudaFuncAttributeMaxDynamicSharedMemorySize, SMEM_BYTES);
    cudaFuncSetAttribute(proj_kernel, cudaFuncAttributeMaxDynamicSharedMemorySize, PROJ_DYN_BYTES);

    prep_kernel<<<VOCABn, 96>>>(wih0, emb);
    rnn_kernel<<<Rn, 256, SMEM_BYTES>>>(x,
        wih0, whh0, bih0, bhh0,
        wih1, whh1, bih1, bhh1,
        wih2, whh2, bih2, bhh2,
        wh2e, bh2e);
    proj_kernel<<<NTOK / PT, 256, PROJ_DYN_BYTES>>>(w_out, b_out, pred);
}